// round 6
// baseline (speedup 1.0000x reference)
#include <cuda_runtime.h>
#include <cstdint>
#include <cstddef>

#define BB 512
#define NT 512
#define NW 16
#define TI 8      // i per tile
#define TJW 4     // j per warp per tile
#define TJT 64    // j per tile = NW*TJW
#define TK 128    // k per tile
#define NIT 64    // BB/TI
#define NJS 8     // BB/TJT
#define NKT 4     // BB/TK
#define NTILE (NIT * NJS * NKT)  // 2048
#define GRID 152

// Face accumulators: {exp-sum, masked-x-sum}
__device__ float2 gF0[BB * BB];  // [j*B+k]: sum over i
__device__ float2 gF1[BB * BB];  // [i*B+k]: sum over j
__device__ float2 gF2[BB * BB];  // [i*B+j]: sum over k
__device__ int gCls[BB];
__device__ int gCnt1;

__device__ __forceinline__ void redAdd2(float2* p, float a, float b) {
    asm volatile("red.global.add.v2.f32 [%0], {%1, %2};"
                 :: "l"(p), "f"(a), "f"(b));
}

__global__ void zero_kernel(float* out) {
    int t = blockIdx.x * blockDim.x + threadIdx.x;  // exactly B*B threads
    float2 z = make_float2(0.f, 0.f);
    gF0[t] = z; gF1[t] = z; gF2[t] = z;
    if (t == 0) { gCnt1 = 0; out[0] = 0.f; }
}

__global__ void class_kernel(const float* __restrict__ target) {
    int i = threadIdx.x;  // 512 threads, 1 block
    // round(t) >= 0  <=>  t >= -0.5 (round-half-even: round(-0.5) = -0 >= 0)
    int b = (target[i] >= -0.5f) ? 1 : 0;
    gCls[i] = b;
    unsigned m = __ballot_sync(0xffffffffu, b);
    if ((i & 31) == 0) atomicAdd(&gCnt1, __popc(m));
}

__global__ __launch_bounds__(NT, 1) void main_kernel(const float* __restrict__ x) {
    const int tid  = threadIdx.x;
    const int lane = tid & 31;
    const int w    = tid >> 5;
    const unsigned FULL = 0xffffffffu;

    __shared__ int scls[BB];
    __shared__ __align__(16) float2 sF1[2][2][NW][TK];  // [buf][i_loc][warp][k] = 32 KB

    for (int t = tid; t < BB; t += NT) scls[t] = gCls[t];
    __syncthreads();

    for (int t = blockIdx.x; t < NTILE; t += GRID) {
        const int it  = t >> 5;          // 0..63
        const int rem = t & 31;
        const int j0  = (rem >> 2) * TJT;
        const int k0  = (rem & 3) * TK;
        const int i0  = it * TI;
        const int kk  = k0 + lane * 4;
        const int jw  = j0 + w * TJW;

        const int ck0 = scls[kk],     ck1 = scls[kk + 1];
        const int ck2 = scls[kk + 2], ck3 = scls[kk + 3];

        // F1 accumulators: [i][k-quad] {E,S} — register resident across tile
        float2 f1[TI][4];
#pragma unroll
        for (int u = 0; u < TI; u++)
#pragma unroll
            for (int q = 0; q < 4; q++) f1[u][q] = make_float2(0.f, 0.f);

        for (int jj = 0; jj < TJW; jj++) {
            const int j  = jw + jj;
            const int cj = scls[j];
            const float* base = x + ((size_t)i0 << 18) + ((size_t)j << 9) + kk;

            float2 f0[4];  // F0 accumulators over the 8 i, this j
#pragma unroll
            for (int q = 0; q < 4; q++) f0[q] = make_float2(0.f, 0.f);

#pragma unroll
            for (int g = 0; g < 2; g++) {
                float4 v[4];
#pragma unroll
                for (int u = 0; u < 4; u++)
                    v[u] = *reinterpret_cast<const float4*>(
                        base + ((size_t)(g * 4 + u) << 18));

#pragma unroll
                for (int u = 0; u < 4; u++) {
                    const int iu = g * 4 + u;
                    const int c  = scls[i0 + iu];
                    const float fij = (cj == c) ? 1.f : 0.f;
                    const float m0 = (ck0 == c) ? 1.f : 0.f;
                    const float m1 = (ck1 == c) ? 1.f : 0.f;
                    const float m2 = (ck2 == c) ? 1.f : 0.f;
                    const float m3 = (ck3 == c) ? 1.f : 0.f;

                    float e0 = __expf(v[u].x), e1 = __expf(v[u].y);
                    float e2 = __expf(v[u].z), e3 = __expf(v[u].w);
                    float s0 = fij * v[u].x, s1 = fij * v[u].y;
                    float s2 = fij * v[u].z, s3 = fij * v[u].w;

                    f0[0].x += e0; f0[0].y += s0;  f1[iu][0].x += e0; f1[iu][0].y += s0;
                    f0[1].x += e1; f0[1].y += s1;  f1[iu][1].x += e1; f1[iu][1].y += s1;
                    f0[2].x += e2; f0[2].y += s2;  f1[iu][2].x += e2; f1[iu][2].y += s2;
                    f0[3].x += e3; f0[3].y += s3;  f1[iu][3].x += e3; f1[iu][3].y += s3;

                    float re = (e0 + e1) + (e2 + e3);
                    float rs = m0 * v[u].x + m1 * v[u].y + m2 * v[u].z + m3 * v[u].w;

                    // packed butterfly: low half reduces re, high half rs (5 SHFL)
                    bool hi = (lane & 16) != 0;
                    float a = hi ? rs : re;
                    float b = hi ? re : rs;
                    a += __shfl_xor_sync(FULL, b, 16);
                    a += __shfl_xor_sync(FULL, a, 8);
                    a += __shfl_xor_sync(FULL, a, 4);
                    a += __shfl_xor_sync(FULL, a, 2);
                    a += __shfl_xor_sync(FULL, a, 1);
                    if ((lane & 15) == 0) {
                        float* fb = reinterpret_cast<float*>(
                            &gF2[((size_t)(i0 + iu) << 9) + j]);
                        atomicAdd(fb + (lane >> 4), a);  // lane0->E, lane16->S
                    }
                }
            }

            // flush F0 for this j (4 contiguous float2 per lane)
#pragma unroll
            for (int q = 0; q < 4; q++)
                redAdd2(&gF0[((size_t)j << 9) + kk + q], f0[q].x, f0[q].y);
        }

        // F1 flush: 4 groups of 2 i, alternating smem buffers, 1 sync per group
#pragma unroll
        for (int g = 0; g < 4; g++) {
            const int buf = g & 1;
#pragma unroll
            for (int u = 0; u < 2; u++) {
                const int iu = g * 2 + u;
                float4* d = reinterpret_cast<float4*>(&sF1[buf][u][w][lane * 4]);
                d[0] = make_float4(f1[iu][0].x, f1[iu][0].y, f1[iu][1].x, f1[iu][1].y);
                d[1] = make_float4(f1[iu][2].x, f1[iu][2].y, f1[iu][3].x, f1[iu][3].y);
            }
            __syncthreads();
            if (tid < 2 * TK) {
                const int kx = tid & (TK - 1);
                const int il = tid >> 7;
                float2 s = sF1[buf][il][0][kx];
#pragma unroll
                for (int ww = 1; ww < NW; ww++) {
                    float2 p = sF1[buf][il][ww][kx];
                    s.x += p.x; s.y += p.y;
                }
                redAdd2(&gF1[((size_t)(i0 + g * 2 + il) << 9) + k0 + kx], s.x, s.y);
            }
        }
    }
}

__global__ void finalize_kernel(float* __restrict__ out) {
    int t = blockIdx.x * blockDim.x + threadIdx.x;  // B*B threads
    int a = t >> 9, b = t & (BB - 1);
    float c = 0.f;
    int ca = gCls[a];
    if (ca == gCls[b]) {
        int n1 = gCnt1;
        float n = (float)((ca == 1) ? n1 : (BB - n1));
        float inv = 1.0f / n;
        float2 f0 = gF0[t], f1 = gF1[t], f2 = gF2[t];
        c = __logf(f0.x) + __logf(f1.x) + __logf(f2.x)
            - (f0.y + f1.y + f2.y) * inv;
    }
    c *= (1.0f / (float)(BB * BB));
#pragma unroll
    for (int o = 16; o > 0; o >>= 1) c += __shfl_xor_sync(0xffffffffu, c, o);
    __shared__ float sacc[16];
    if ((threadIdx.x & 31) == 0) sacc[threadIdx.x >> 5] = c;
    __syncthreads();
    if (threadIdx.x < 16) {
        float v = sacc[threadIdx.x];
#pragma unroll
        for (int o = 8; o > 0; o >>= 1) v += __shfl_xor_sync(0xffffu, v, o);
        if (threadIdx.x == 0) atomicAdd(out, v);
    }
}

extern "C" void kernel_launch(void* const* d_in, const int* in_sizes, int n_in,
                              void* d_out, int out_size) {
    const float* cube   = (const float*)d_in[0];
    const float* target = (const float*)d_in[1];
    if (n_in >= 2 && in_sizes[0] < in_sizes[1]) {  // defensive order check
        cube   = (const float*)d_in[1];
        target = (const float*)d_in[0];
    }
    float* out = (float*)d_out;

    zero_kernel<<<BB * BB / 512, 512>>>(out);
    class_kernel<<<1, BB>>>(target);
    main_kernel<<<GRID, NT>>>(cube);
    finalize_kernel<<<BB * BB / 512, 512>>>(out);
}

// round 7
// speedup vs baseline: 1.7305x; 1.7305x over previous
#include <cuda_runtime.h>
#include <cstdint>
#include <cstddef>

#define BB 512
#define NT 512
#define NW 16
#define TJ 16    // j per tile (NW warps x 1 row)
#define TK 128   // k per tile
#define TI 16    // i per tile
#define NJT 32
#define NKT 4
#define NIT 32
#define NTILE (NJT * NKT * NIT)  // 4096
#define GRID 296
#define SMEM_BYTES (2048 + 2 * 2 * NW * TK * 8)  // scls + 4-way F1 staging = 67584

// Face accumulators: {exp-sum, masked-x-sum}
__device__ float2 gF0[BB * BB];  // [j*B+k]: sum over i
__device__ float2 gF1[BB * BB];  // [i*B+k]: sum over j
__device__ float2 gF2[BB * BB];  // [i*B+j]: sum over k
__device__ int gCls[BB];
__device__ int gCnt1;

__device__ __forceinline__ void redAdd2(float2* p, float a, float b) {
    asm volatile("red.global.add.v2.f32 [%0], {%1, %2};"
                 :: "l"(p), "f"(a), "f"(b));
}
__device__ __forceinline__ unsigned long long pk2(float lo, float hi) {
    unsigned long long r;
    asm("mov.b64 %0, {%1, %2};" : "=l"(r) : "f"(lo), "f"(hi));
    return r;
}
__device__ __forceinline__ void fadd2(unsigned long long& a, unsigned long long b) {
    asm("add.rn.f32x2 %0, %0, %1;" : "+l"(a) : "l"(b));
}
__device__ __forceinline__ float lo2(unsigned long long a) {
    float f; asm("{.reg .f32 h; mov.b64 {%0, h}, %1;}" : "=f"(f) : "l"(a)); return f;
}
__device__ __forceinline__ float hi2(unsigned long long a) {
    float f; asm("{.reg .f32 l; mov.b64 {l, %0}, %1;}" : "=f"(f) : "l"(a)); return f;
}

__global__ void zero_kernel(float* out) {
    int t = blockIdx.x * blockDim.x + threadIdx.x;  // exactly B*B threads
    float2 z = make_float2(0.f, 0.f);
    gF0[t] = z; gF1[t] = z; gF2[t] = z;
    if (t == 0) { gCnt1 = 0; out[0] = 0.f; }
}

__global__ void class_kernel(const float* __restrict__ target) {
    int i = threadIdx.x;  // 512 threads, 1 block
    // round(t) >= 0  <=>  t >= -0.5 (round-half-even: round(-0.5) = -0 >= 0)
    int b = (target[i] >= -0.5f) ? 1 : 0;
    gCls[i] = b;
    unsigned m = __ballot_sync(0xffffffffu, b);
    if ((i & 31) == 0) atomicAdd(&gCnt1, __popc(m));
}

__device__ __forceinline__ size_t tile_off(int t, int w, int lane) {
    int it = t >> 7;          // i-split (0..31)
    int rem = t & 127;
    int jt = rem >> 2;        // j tile (0..31)
    int kt = rem & 3;         // k tile (0..3)
    return ((size_t)(it * TI) << 18)
         + ((size_t)(jt * TJ + w) << 9)
         + (size_t)(kt * TK + lane * 4);
}

__device__ __forceinline__ void process_row(
    float4 v, int ci, int cj, int ck0, int ck1, int ck2, int ck3,
    unsigned long long* a0, unsigned long long* dst, int lane, size_t f2idx)
{
    const float fij = (cj == ci) ? 1.f : 0.f;
    const float m0 = (ck0 == ci) ? 1.f : 0.f;
    const float m1 = (ck1 == ci) ? 1.f : 0.f;
    const float m2 = (ck2 == ci) ? 1.f : 0.f;
    const float m3 = (ck3 == ci) ? 1.f : 0.f;

    float e0 = __expf(v.x), e1 = __expf(v.y), e2 = __expf(v.z), e3 = __expf(v.w);
    unsigned long long t0 = pk2(e0, fij * v.x);
    unsigned long long t1 = pk2(e1, fij * v.y);
    unsigned long long t2 = pk2(e2, fij * v.z);
    unsigned long long t3 = pk2(e3, fij * v.w);
    fadd2(a0[0], t0); fadd2(a0[1], t1); fadd2(a0[2], t2); fadd2(a0[3], t3);

    // stage F1 partials (this row's {E,S} per k) — two 128-bit stores
    ulonglong2* d = reinterpret_cast<ulonglong2*>(dst + lane * 4);
    d[0] = make_ulonglong2(t0, t1);
    d[1] = make_ulonglong2(t2, t3);

    // F2: packed butterfly, 5 SHFL reduce {re, rs} over 128 k
    float re = (e0 + e1) + (e2 + e3);
    float rs = m0 * v.x + m1 * v.y + m2 * v.z + m3 * v.w;
    const unsigned FULL = 0xffffffffu;
    bool hi = (lane & 16) != 0;
    float a = hi ? rs : re;
    float b = hi ? re : rs;
    a += __shfl_xor_sync(FULL, b, 16);
    a += __shfl_xor_sync(FULL, a, 8);
    a += __shfl_xor_sync(FULL, a, 4);
    a += __shfl_xor_sync(FULL, a, 2);
    a += __shfl_xor_sync(FULL, a, 1);
    if ((lane & 15) == 0)  // lane0 -> E, lane16 -> S (adjacent floats)
        atomicAdd(reinterpret_cast<float*>(gF2) + f2idx * 2 + (lane >> 4), a);
}

__global__ __launch_bounds__(NT, 2) void main_kernel(const float* __restrict__ x) {
    const int tid  = threadIdx.x;
    const int lane = tid & 31;
    const int w    = tid >> 5;

    extern __shared__ char smem[];
    int* scls = reinterpret_cast<int*>(smem);
    // F1 staging: [pairbuf 2][i-parity 2][warp 16][k 128] of {E,S} ull
    unsigned long long* sF1 = reinterpret_cast<unsigned long long*>(smem + 2048);

    for (int t = tid; t < BB; t += NT) scls[t] = gCls[t];
    __syncthreads();

    for (int t = blockIdx.x; t < NTILE; t += GRID) {
        const int it  = t >> 7;
        const int rem = t & 127;
        const int j0  = (rem >> 2) * TJ;
        const int k0  = (rem & 3) * TK;
        const int i0  = it * TI;
        const int j   = j0 + w;
        const int kk  = k0 + lane * 4;

        const int cj  = scls[j];
        const int ck0 = scls[kk],     ck1 = scls[kk + 1];
        const int ck2 = scls[kk + 2], ck3 = scls[kk + 3];

        unsigned long long a0[4] = {0ull, 0ull, 0ull, 0ull};  // bits0 == (0.f,0.f)

        const float* p = x + ((size_t)i0 << 18) + ((size_t)j << 9) + kk;
        float4 vA = *reinterpret_cast<const float4*>(p);
        float4 vB = *reinterpret_cast<const float4*>(p + (1 << 18));

        for (int pr = 0; pr < TI / 2; pr++) {
            // depth-2 prefetch: both rows of the next pair
            const float* pn;
            if (pr + 1 < TI / 2) pn = p + (2 << 18);
            else {
                int tn = t + GRID;
                pn = (tn < NTILE) ? (x + tile_off(tn, w, lane)) : p;
            }
            float4 nA = *reinterpret_cast<const float4*>(pn);
            float4 nB = *reinterpret_cast<const float4*>(pn + (1 << 18));

            const int iA = i0 + 2 * pr, iB = iA + 1;
            const int ps = pr & 1;
            unsigned long long* bufA = sF1 + (size_t)(ps * 2 + 0) * (NW * TK) + (size_t)w * TK;
            unsigned long long* bufB = sF1 + (size_t)(ps * 2 + 1) * (NW * TK) + (size_t)w * TK;

            process_row(vA, scls[iA], cj, ck0, ck1, ck2, ck3, a0, bufA, lane, (size_t)iA * BB + j);
            process_row(vB, scls[iB], cj, ck0, ck1, ck2, ck3, a0, bufB, lane, (size_t)iB * BB + j);
            __syncthreads();

            if (tid < 2 * TK) {  // warps 0..7 gather; warps 8..15 run ahead
                const int il = tid >> 7, kx = tid & (TK - 1);
                const unsigned long long* g = sF1 + (size_t)(ps * 2 + il) * (NW * TK) + kx;
                unsigned long long s = g[0];
#pragma unroll
                for (int ww = 1; ww < NW; ww++) fadd2(s, g[(size_t)ww * TK]);
                redAdd2(&gF1[(size_t)(iA + il) * BB + k0 + kx], lo2(s), hi2(s));
            }

            vA = nA; vB = nB; p = pn;
        }

        // flush F0 for this (j, k-quad) over the tile's 16 i
#pragma unroll
        for (int q = 0; q < 4; q++)
            redAdd2(&gF0[((size_t)j << 9) + kk + q], lo2(a0[q]), hi2(a0[q]));
    }
}

__global__ void finalize_kernel(float* __restrict__ out) {
    int t = blockIdx.x * blockDim.x + threadIdx.x;  // B*B threads
    int a = t >> 9, b = t & (BB - 1);
    float c = 0.f;
    int ca = gCls[a];
    if (ca == gCls[b]) {
        int n1 = gCnt1;
        float n = (float)((ca == 1) ? n1 : (BB - n1));
        float inv = 1.0f / n;
        float2 f0 = gF0[t], f1 = gF1[t], f2 = gF2[t];
        c = __logf(f0.x) + __logf(f1.x) + __logf(f2.x)
            - (f0.y + f1.y + f2.y) * inv;
    }
    c *= (1.0f / (float)(BB * BB));
#pragma unroll
    for (int o = 16; o > 0; o >>= 1) c += __shfl_xor_sync(0xffffffffu, c, o);
    __shared__ float sacc[16];
    if ((threadIdx.x & 31) == 0) sacc[threadIdx.x >> 5] = c;
    __syncthreads();
    if (threadIdx.x < 16) {
        float v = sacc[threadIdx.x];
#pragma unroll
        for (int o = 8; o > 0; o >>= 1) v += __shfl_xor_sync(0xffffu, v, o);
        if (threadIdx.x == 0) atomicAdd(out, v);
    }
}

extern "C" void kernel_launch(void* const* d_in, const int* in_sizes, int n_in,
                              void* d_out, int out_size) {
    const float* cube   = (const float*)d_in[0];
    const float* target = (const float*)d_in[1];
    if (n_in >= 2 && in_sizes[0] < in_sizes[1]) {  // defensive order check
        cube   = (const float*)d_in[1];
        target = (const float*)d_in[0];
    }
    float* out = (float*)d_out;

    static bool attr_set = false;
    if (!attr_set) {
        cudaFuncSetAttribute(main_kernel,
                             cudaFuncAttributeMaxDynamicSharedMemorySize, SMEM_BYTES);
        attr_set = true;
    }

    zero_kernel<<<BB * BB / 512, 512>>>(out);
    class_kernel<<<1, BB>>>(target);
    main_kernel<<<GRID, NT, SMEM_BYTES>>>(cube);
    finalize_kernel<<<BB * BB / 512, 512>>>(out);
}